// round 1
// baseline (speedup 1.0000x reference)
#include <cuda_runtime.h>
#include <math.h>

#define L_TOK 131072
#define C_DIM 192
#define QKV_DIM 576
#define FF_DIM 768
#define NWIN 2048

__device__ float g_bufA[(size_t)L_TOK * C_DIM];
__device__ float g_qkv [(size_t)L_TOK * QKV_DIM];
__device__ float g_obuf[(size_t)L_TOK * C_DIM];
__device__ float g_bufT[(size_t)L_TOK * FF_DIM];

__global__ void ln_kernel(const float* __restrict__ x,
                          const float* __restrict__ g,
                          const float* __restrict__ b,
                          float* __restrict__ out)
{
    int row  = blockIdx.x * 8 + threadIdx.y;
    int lane = threadIdx.x;
    const float* xr = x + (size_t)row * C_DIM;
    float v[6];
    float s = 0.f;
#pragma unroll
    for (int i = 0; i < 6; i++) { v[i] = xr[lane + i * 32]; s += v[i]; }
#pragma unroll
    for (int o = 16; o; o >>= 1) s += __shfl_xor_sync(0xffffffffu, s, o);
    float mu = s * (1.0f / 192.0f);
    float vs = 0.f;
#pragma unroll
    for (int i = 0; i < 6; i++) { float d = v[i] - mu; vs += d * d; }
#pragma unroll
    for (int o = 16; o; o >>= 1) vs += __shfl_xor_sync(0xffffffffu, vs, o);
    float rstd = rsqrtf(vs * (1.0f / 192.0f) + 1e-5f);
    float* orow = out + (size_t)row * C_DIM;
#pragma unroll
    for (int i = 0; i < 6; i++) {
        int c = lane + i * 32;
        orow[c] = (v[i] - mu) * rstd * g[c] + b[c];
    }
}

template<bool GELU, bool RES>
__global__ __launch_bounds__(256)
void gemm_kernel(const float* __restrict__ A, const float* __restrict__ B,
                 const float* __restrict__ bias, const float* __restrict__ res,
                 float* __restrict__ Cout, int M, int N, int K)
{
    const int BM = 128, BN = 64, BK = 16;
    __shared__ float As[BK][BM];
    __shared__ float Bs[BK][BN];

    int bm = blockIdx.y * BM;
    int bn = blockIdx.x * BN;
    int tid = threadIdx.x;
    int tm = tid >> 4;
    int tn = tid & 15;

    float acc[8][4];
#pragma unroll
    for (int i = 0; i < 8; i++)
#pragma unroll
        for (int j = 0; j < 4; j++) acc[i][j] = 0.f;

    for (int k0 = 0; k0 < K; k0 += BK) {
#pragma unroll
        for (int l = 0; l < 2; l++) {
            int idx = tid * 2 + l;
            int r   = idx >> 2;
            int c4  = (idx & 3) * 4;
            float4 v = *(const float4*)(A + (size_t)(bm + r) * K + k0 + c4);
            As[c4 + 0][r] = v.x; As[c4 + 1][r] = v.y;
            As[c4 + 2][r] = v.z; As[c4 + 3][r] = v.w;
        }
        {
            int r  = tid >> 4;
            int c4 = (tid & 15) * 4;
            *(float4*)(&Bs[r][c4]) = *(const float4*)(B + (size_t)(k0 + r) * N + bn + c4);
        }
        __syncthreads();
#pragma unroll
        for (int kk = 0; kk < BK; kk++) {
            float a[8], bb[4];
#pragma unroll
            for (int i = 0; i < 8; i++) a[i] = As[kk][tm * 8 + i];
#pragma unroll
            for (int j = 0; j < 4; j++) bb[j] = Bs[kk][tn * 4 + j];
#pragma unroll
            for (int i = 0; i < 8; i++)
#pragma unroll
                for (int j = 0; j < 4; j++) acc[i][j] += a[i] * bb[j];
        }
        __syncthreads();
    }

    int col = bn + tn * 4;
    float4 bv = *(const float4*)(bias + col);
#pragma unroll
    for (int i = 0; i < 8; i++) {
        int row = bm + tm * 8 + i;
        float4 o;
        o.x = acc[i][0] + bv.x;
        o.y = acc[i][1] + bv.y;
        o.z = acc[i][2] + bv.z;
        o.w = acc[i][3] + bv.w;
        if (GELU) {
            o.x = 0.5f * o.x * (1.0f + erff(o.x * 0.70710678118654752f));
            o.y = 0.5f * o.y * (1.0f + erff(o.y * 0.70710678118654752f));
            o.z = 0.5f * o.z * (1.0f + erff(o.z * 0.70710678118654752f));
            o.w = 0.5f * o.w * (1.0f + erff(o.w * 0.70710678118654752f));
        }
        if (RES) {
            float4 r = *(const float4*)(res + (size_t)row * N + col);
            o.x += r.x; o.y += r.y; o.z += r.z; o.w += r.w;
        }
        *(float4*)(Cout + (size_t)row * N + col) = o;
    }
}

__global__ __launch_bounds__(256)
void attn_kernel(const float* __restrict__ qkv, const float* __restrict__ rpb,
                 float* __restrict__ O, int shifted)
{
    __shared__ float qs[64][33];
    __shared__ float ks[64][33];
    __shared__ float vsm[64][33];
    __shared__ float sc[64][65];
    __shared__ int tok[64];
    __shared__ int regid[64];

    int win = blockIdx.x;
    int ws = win >> 8;
    int wh = (win >> 4) & 15;
    int ww = win & 15;
    int tid = threadIdx.x;

    if (tid < 64) {
        int i = tid >> 4, j = (tid >> 2) & 3, k = tid & 3;
        int cs = ws * 4 + i, ch = wh * 4 + j, cw = ww * 4 + k;
        int sg, hg, wg;
        if (shifted) { sg = (cs + 2) & 31; hg = (ch + 2) & 63; wg = (cw + 2) & 63; }
        else         { sg = cs;            hg = ch;            wg = cw; }
        tok[tid] = (sg * 64 + hg) * 64 + wg;
        int rs = cs < 28 ? 0 : (cs < 30 ? 1 : 2);
        int rh = ch < 60 ? 0 : (ch < 62 ? 1 : 2);
        int rw = cw < 60 ? 0 : (cw < 62 ? 1 : 2);
        regid[tid] = rs * 9 + rh * 3 + rw;
    }
    __syncthreads();

    const float scale = 0.17677669529663687f;
    int n  = tid >> 2;
    int d0 = (tid & 3) * 8;

    for (int h = 0; h < 6; h++) {
        {
            const float* base = qkv + (size_t)tok[n] * QKV_DIM + h * 32 + d0;
            float4 a0 = *(const float4*)(base);
            float4 a1 = *(const float4*)(base + 4);
            qs[n][d0+0] = a0.x*scale; qs[n][d0+1] = a0.y*scale;
            qs[n][d0+2] = a0.z*scale; qs[n][d0+3] = a0.w*scale;
            qs[n][d0+4] = a1.x*scale; qs[n][d0+5] = a1.y*scale;
            qs[n][d0+6] = a1.z*scale; qs[n][d0+7] = a1.w*scale;
            float4 b0 = *(const float4*)(base + 192);
            float4 b1 = *(const float4*)(base + 196);
            ks[n][d0+0] = b0.x; ks[n][d0+1] = b0.y; ks[n][d0+2] = b0.z; ks[n][d0+3] = b0.w;
            ks[n][d0+4] = b1.x; ks[n][d0+5] = b1.y; ks[n][d0+6] = b1.z; ks[n][d0+7] = b1.w;
            float4 c0 = *(const float4*)(base + 384);
            float4 c1 = *(const float4*)(base + 388);
            vsm[n][d0+0] = c0.x; vsm[n][d0+1] = c0.y; vsm[n][d0+2] = c0.z; vsm[n][d0+3] = c0.w;
            vsm[n][d0+4] = c1.x; vsm[n][d0+5] = c1.y; vsm[n][d0+6] = c1.z; vsm[n][d0+7] = c1.w;
        }
        __syncthreads();

        {
            int in_ = n >> 4, jn = (n >> 2) & 3, kn = n & 3;
#pragma unroll 4
            for (int t = 0; t < 16; t++) {
                int m = (tid & 3) * 16 + t;
                float s = 0.f;
#pragma unroll
                for (int d = 0; d < 32; d++) s += qs[n][d] * ks[m][d];
                int im = m >> 4, jm = (m >> 2) & 3, km = m & 3;
                int idx = (in_ - im + 3) * 49 + (jn - jm + 3) * 7 + (kn - km + 3);
                s += rpb[idx * 6 + h];
                if (shifted && (regid[n] != regid[m])) s -= 100.f;
                sc[n][m] = s;
            }
        }
        __syncthreads();

        if (tid < 64) {
            float mx = -1e30f;
#pragma unroll 8
            for (int m = 0; m < 64; m++) mx = fmaxf(mx, sc[tid][m]);
            float sum = 0.f;
#pragma unroll 8
            for (int m = 0; m < 64; m++) {
                float e = __expf(sc[tid][m] - mx);
                sc[tid][m] = e; sum += e;
            }
            float inv = 1.0f / sum;
#pragma unroll 8
            for (int m = 0; m < 64; m++) sc[tid][m] *= inv;
        }
        __syncthreads();

        {
            float o[8] = {0,0,0,0,0,0,0,0};
#pragma unroll 8
            for (int m = 0; m < 64; m++) {
                float p = sc[n][m];
#pragma unroll
                for (int q = 0; q < 8; q++) o[q] += p * vsm[m][d0 + q];
            }
            float* op = O + (size_t)tok[n] * C_DIM + h * 32 + d0;
#pragma unroll
            for (int q = 0; q < 8; q++) op[q] = o[q];
        }
        __syncthreads();
    }
}

static void run_block(const float* Xin, float* Xout,
                      const float* g1, const float* b1,
                      const float* qw, const float* qb, const float* rpb,
                      const float* pw, const float* pb,
                      const float* g2, const float* b2,
                      const float* f1w, const float* f1b,
                      const float* f2w, const float* f2b,
                      int shifted,
                      float* bufA, float* qkv, float* obuf, float* bufT)
{
    dim3 lnBlk(32, 8);
    int lnGrid = L_TOK / 8;

    ln_kernel<<<lnGrid, lnBlk>>>(Xin, g1, b1, bufA);
    gemm_kernel<false, false><<<dim3(QKV_DIM / 64, L_TOK / 128), 256>>>(
        bufA, qw, qb, nullptr, qkv, L_TOK, QKV_DIM, C_DIM);
    attn_kernel<<<NWIN, 256>>>(qkv, rpb, obuf, shifted);
    gemm_kernel<false, true><<<dim3(C_DIM / 64, L_TOK / 128), 256>>>(
        obuf, pw, pb, Xin, Xout, L_TOK, C_DIM, C_DIM);
    ln_kernel<<<lnGrid, lnBlk>>>(Xout, g2, b2, bufA);
    gemm_kernel<true, false><<<dim3(FF_DIM / 64, L_TOK / 128), 256>>>(
        bufA, f1w, f1b, nullptr, bufT, L_TOK, FF_DIM, C_DIM);
    gemm_kernel<false, true><<<dim3(C_DIM / 64, L_TOK / 128), 256>>>(
        bufT, f2w, f2b, Xout, Xout, L_TOK, C_DIM, FF_DIM);
}

extern "C" void kernel_launch(void* const* d_in, const int* in_sizes, int n_in,
                              void* d_out, int out_size)
{
    (void)in_sizes; (void)n_in; (void)out_size;
    const float* x = (const float*)d_in[0];
    float* out = (float*)d_out;

    float *bufA, *qkv, *obuf, *bufT;
    cudaGetSymbolAddress((void**)&bufA, g_bufA);
    cudaGetSymbolAddress((void**)&qkv,  g_qkv);
    cudaGetSymbolAddress((void**)&obuf, g_obuf);
    cudaGetSymbolAddress((void**)&bufT, g_bufT);

    run_block(x, out,
              (const float*)d_in[1],  (const float*)d_in[2],
              (const float*)d_in[3],  (const float*)d_in[4],  (const float*)d_in[5],
              (const float*)d_in[6],  (const float*)d_in[7],
              (const float*)d_in[8],  (const float*)d_in[9],
              (const float*)d_in[10], (const float*)d_in[11],
              (const float*)d_in[12], (const float*)d_in[13],
              0, bufA, qkv, obuf, bufT);

    run_block(out, out,
              (const float*)d_in[14], (const float*)d_in[15],
              (const float*)d_in[16], (const float*)d_in[17], (const float*)d_in[18],
              (const float*)d_in[19], (const float*)d_in[20],
              (const float*)d_in[21], (const float*)d_in[22],
              (const float*)d_in[23], (const float*)d_in[24],
              (const float*)d_in[25], (const float*)d_in[26],
              1, bufA, qkv, obuf, bufT);
}

// round 2
// speedup vs baseline: 1.9044x; 1.9044x over previous
#include <cuda_runtime.h>
#include <math.h>

#define L_TOK 131072
#define C_DIM 192
#define QKV_DIM 576
#define FF_DIM 768
#define NWIN 2048

// scratch (device globals; no allocation allowed)
__device__ float g_bufA[(size_t)L_TOK * C_DIM];    // LN out (tf32-rounded)
__device__ float g_qkv [(size_t)L_TOK * QKV_DIM];  // QKV
__device__ float g_obuf[(size_t)L_TOK * C_DIM];    // attn out (tf32-rounded)
__device__ float g_bufT[(size_t)L_TOK * FF_DIM];   // MLP hidden (tf32-rounded)
__device__ float g_wtf [884736];                   // tf32 weight copies (2 blocks)

__device__ __forceinline__ float tf32r(float x) {
    unsigned u;
    asm("cvt.rna.tf32.f32 %0, %1;" : "=r"(u) : "f"(x));
    return __uint_as_float(u);
}

__device__ __forceinline__ void cp_async16(void* smem, const void* gmem) {
    unsigned saddr = (unsigned)__cvta_generic_to_shared(smem);
    asm volatile("cp.async.cg.shared.global [%0], [%1], 16;\n" :: "r"(saddr), "l"(gmem));
}

// ---------------------------------------------------------------------------
__global__ void cvt_tf32_kernel(const float* __restrict__ in,
                                float* __restrict__ out, int n)
{
    int i = blockIdx.x * 256 + threadIdx.x;
    if (i < n) out[i] = tf32r(in[i]);
}

// ---------------------------------------------------------------------------
// LayerNorm, one row per warp; output tf32-rounded (feeds GEMM A only)
// ---------------------------------------------------------------------------
__global__ void ln_kernel(const float* __restrict__ x,
                          const float* __restrict__ g,
                          const float* __restrict__ b,
                          float* __restrict__ out)
{
    int row  = blockIdx.x * 8 + threadIdx.y;
    int lane = threadIdx.x;
    const float* xr = x + (size_t)row * C_DIM;
    float v[6];
    float s = 0.f;
#pragma unroll
    for (int i = 0; i < 6; i++) { v[i] = xr[lane + i * 32]; s += v[i]; }
#pragma unroll
    for (int o = 16; o; o >>= 1) s += __shfl_xor_sync(0xffffffffu, s, o);
    float mu = s * (1.0f / 192.0f);
    float vs = 0.f;
#pragma unroll
    for (int i = 0; i < 6; i++) { float d = v[i] - mu; vs += d * d; }
#pragma unroll
    for (int o = 16; o; o >>= 1) vs += __shfl_xor_sync(0xffffffffu, vs, o);
    float rstd = rsqrtf(vs * (1.0f / 192.0f) + 1e-5f);
    float* orow = out + (size_t)row * C_DIM;
#pragma unroll
    for (int i = 0; i < 6; i++) {
        int c = lane + i * 32;
        orow[c] = tf32r((v[i] - mu) * rstd * g[c] + b[c]);
    }
}

// ---------------------------------------------------------------------------
// TF32 tensor-core GEMM: C[M,N] = A[M,K]@B[K,N] + bias (+GELU)(+res)(+tf32 out)
// BM=128, BN=64, BK=24. 256 thr, 8 warps (4x2), warp tile 32x32 (2x4 mma).
// A,B assumed already tf32-valued (pre-rounded). fp32 accumulate.
// ---------------------------------------------------------------------------
#define GBM 128
#define GBN 64
#define GBK 24
#define ASTR 28   // conflict-free: bank(m,k)=(28m+k)%32 distinct over fragment
#define BSTR 72   // conflict-free: bank(k,n)=(8k+n)%32 distinct over fragment

template<bool DOGELU, bool RES, bool OTF>
__global__ __launch_bounds__(256)
void gemm_tf32(const float* __restrict__ A, const float* __restrict__ B,
               const float* __restrict__ bias, const float* __restrict__ res,
               float* __restrict__ Cout, int M, int N, int K)
{
    __shared__ float As[2][GBM * ASTR];
    __shared__ float Bs[2][GBK * BSTR];

    int tid = threadIdx.x;
    int bm = blockIdx.y * GBM;
    int bn = blockIdx.x * GBN;
    int wid = tid >> 5, lane = tid & 31;
    int wm = (wid & 3) * 32, wn = (wid >> 2) * 32;
    int g = lane >> 2, t = lane & 3;

    float acc[2][4][4];
#pragma unroll
    for (int a = 0; a < 2; a++)
#pragma unroll
        for (int b2 = 0; b2 < 4; b2++)
#pragma unroll
            for (int c = 0; c < 4; c++) acc[a][b2][c] = 0.f;

    auto loadA = [&](int stage, int k0) {
#pragma unroll
        for (int l = 0; l < 3; l++) {
            int idx = tid + l * 256;      // 0..767  (128 rows x 6 float4)
            int m  = idx / 6;
            int k4 = (idx % 6) * 4;
            cp_async16(&As[stage][m * ASTR + k4],
                       A + (size_t)(bm + m) * K + k0 + k4);
        }
    };
    auto loadB = [&](int stage, int k0) {
#pragma unroll
        for (int l = 0; l < 2; l++) {
            int idx = tid + l * 256;      // 0..383  (24 rows x 16 float4)
            if (idx < 384) {
                int r  = idx >> 4;
                int c4 = (idx & 15) * 4;
                cp_async16(&Bs[stage][r * BSTR + c4],
                           B + (size_t)(k0 + r) * N + bn + c4);
            }
        }
    };

    int nk = K / GBK;
    loadA(0, 0); loadB(0, 0);
    asm volatile("cp.async.commit_group;");

    for (int kb = 0; kb < nk; kb++) {
        if (kb + 1 < nk) {
            loadA((kb + 1) & 1, (kb + 1) * GBK);
            loadB((kb + 1) & 1, (kb + 1) * GBK);
            asm volatile("cp.async.commit_group;");
            asm volatile("cp.async.wait_group 1;");
        } else {
            asm volatile("cp.async.wait_group 0;");
        }
        __syncthreads();

        const float* as = As[kb & 1];
        const float* bs = Bs[kb & 1];
#pragma unroll
        for (int ks = 0; ks < 3; ks++) {
            unsigned af[2][4], bf[4][2];
#pragma unroll
            for (int mt = 0; mt < 2; mt++) {
                int mb = wm + mt * 16;
                af[mt][0] = __float_as_uint(as[(mb + g    ) * ASTR + ks * 8 + t    ]);
                af[mt][1] = __float_as_uint(as[(mb + g + 8) * ASTR + ks * 8 + t    ]);
                af[mt][2] = __float_as_uint(as[(mb + g    ) * ASTR + ks * 8 + t + 4]);
                af[mt][3] = __float_as_uint(as[(mb + g + 8) * ASTR + ks * 8 + t + 4]);
            }
#pragma unroll
            for (int nt = 0; nt < 4; nt++) {
                int nb = wn + nt * 8 + g;
                bf[nt][0] = __float_as_uint(bs[(ks * 8 + t    ) * BSTR + nb]);
                bf[nt][1] = __float_as_uint(bs[(ks * 8 + t + 4) * BSTR + nb]);
            }
#pragma unroll
            for (int mt = 0; mt < 2; mt++)
#pragma unroll
                for (int nt = 0; nt < 4; nt++) {
                    asm volatile(
                        "mma.sync.aligned.m16n8k8.row.col.f32.tf32.tf32.f32 "
                        "{%0,%1,%2,%3},{%4,%5,%6,%7},{%8,%9},{%0,%1,%2,%3};"
                        : "+f"(acc[mt][nt][0]), "+f"(acc[mt][nt][1]),
                          "+f"(acc[mt][nt][2]), "+f"(acc[mt][nt][3])
                        : "r"(af[mt][0]), "r"(af[mt][1]),
                          "r"(af[mt][2]), "r"(af[mt][3]),
                          "r"(bf[nt][0]), "r"(bf[nt][1]));
                }
        }
        __syncthreads();
    }

    // epilogue: c0,c1 -> (row g, cols 2t,2t+1); c2,c3 -> (row g+8, ...)
#pragma unroll
    for (int mt = 0; mt < 2; mt++)
#pragma unroll
        for (int nt = 0; nt < 4; nt++) {
            int col = bn + wn + nt * 8 + 2 * t;
            float2 bv = *(const float2*)(bias + col);
#pragma unroll
            for (int hf = 0; hf < 2; hf++) {
                int row = bm + wm + mt * 16 + g + hf * 8;
                float x0 = acc[mt][nt][hf * 2 + 0] + bv.x;
                float x1 = acc[mt][nt][hf * 2 + 1] + bv.y;
                if (DOGELU) {
                    x0 = 0.5f * x0 * (1.0f + erff(x0 * 0.70710678118654752f));
                    x1 = 0.5f * x1 * (1.0f + erff(x1 * 0.70710678118654752f));
                }
                if (RES) {
                    float2 r = *(const float2*)(res + (size_t)row * N + col);
                    x0 += r.x; x1 += r.y;
                }
                if (OTF) { x0 = tf32r(x0); x1 = tf32r(x1); }
                *(float2*)(Cout + (size_t)row * N + col) = make_float2(x0, x1);
            }
        }
}

// ---------------------------------------------------------------------------
// Window attention (fp32), output tf32-rounded (feeds proj GEMM A)
// ---------------------------------------------------------------------------
__global__ __launch_bounds__(256)
void attn_kernel(const float* __restrict__ qkv, const float* __restrict__ rpb,
                 float* __restrict__ O, int shifted)
{
    __shared__ float qs[64][33];
    __shared__ float ks[64][33];
    __shared__ float vsm[64][33];
    __shared__ float sc[64][65];
    __shared__ int tok[64];
    __shared__ int regid[64];

    int win = blockIdx.x;
    int ws = win >> 8;
    int wh = (win >> 4) & 15;
    int ww = win & 15;
    int tid = threadIdx.x;

    if (tid < 64) {
        int i = tid >> 4, j = (tid >> 2) & 3, k = tid & 3;
        int cs = ws * 4 + i, ch = wh * 4 + j, cw = ww * 4 + k;
        int sg, hg, wg;
        if (shifted) { sg = (cs + 2) & 31; hg = (ch + 2) & 63; wg = (cw + 2) & 63; }
        else         { sg = cs;            hg = ch;            wg = cw; }
        tok[tid] = (sg * 64 + hg) * 64 + wg;
        int rs = cs < 28 ? 0 : (cs < 30 ? 1 : 2);
        int rh = ch < 60 ? 0 : (ch < 62 ? 1 : 2);
        int rw = cw < 60 ? 0 : (cw < 62 ? 1 : 2);
        regid[tid] = rs * 9 + rh * 3 + rw;
    }
    __syncthreads();

    const float scale = 0.17677669529663687f;
    int n  = tid >> 2;
    int d0 = (tid & 3) * 8;

    for (int h = 0; h < 6; h++) {
        {
            const float* base = qkv + (size_t)tok[n] * QKV_DIM + h * 32 + d0;
            float4 a0 = *(const float4*)(base);
            float4 a1 = *(const float4*)(base + 4);
            qs[n][d0+0] = a0.x*scale; qs[n][d0+1] = a0.y*scale;
            qs[n][d0+2] = a0.z*scale; qs[n][d0+3] = a0.w*scale;
            qs[n][d0+4] = a1.x*scale; qs[n][d0+5] = a1.y*scale;
            qs[n][d0+6] = a1.z*scale; qs[n][d0+7] = a1.w*scale;
            float4 b0 = *(const float4*)(base + 192);
            float4 b1 = *(const float4*)(base + 196);
            ks[n][d0+0] = b0.x; ks[n][d0+1] = b0.y; ks[n][d0+2] = b0.z; ks[n][d0+3] = b0.w;
            ks[n][d0+4] = b1.x; ks[n][d0+5] = b1.y; ks[n][d0+6] = b1.z; ks[n][d0+7] = b1.w;
            float4 c0 = *(const float4*)(base + 384);
            float4 c1 = *(const float4*)(base + 388);
            vsm[n][d0+0] = c0.x; vsm[n][d0+1] = c0.y; vsm[n][d0+2] = c0.z; vsm[n][d0+3] = c0.w;
            vsm[n][d0+4] = c1.x; vsm[n][d0+5] = c1.y; vsm[n][d0+6] = c1.z; vsm[n][d0+7] = c1.w;
        }
        __syncthreads();

        {
            int in_ = n >> 4, jn = (n >> 2) & 3, kn = n & 3;
#pragma unroll 4
            for (int tI = 0; tI < 16; tI++) {
                int m = (tid & 3) * 16 + tI;
                float s = 0.f;
#pragma unroll
                for (int d = 0; d < 32; d++) s += qs[n][d] * ks[m][d];
                int im = m >> 4, jm = (m >> 2) & 3, km = m & 3;
                int idx = (in_ - im + 3) * 49 + (jn - jm + 3) * 7 + (kn - km + 3);
                s += rpb[idx * 6 + h];
                if (shifted && (regid[n] != regid[m])) s -= 100.f;
                sc[n][m] = s;
            }
        }
        __syncthreads();

        if (tid < 64) {
            float mx = -1e30f;
#pragma unroll 8
            for (int m = 0; m < 64; m++) mx = fmaxf(mx, sc[tid][m]);
            float sum = 0.f;
#pragma unroll 8
            for (int m = 0; m < 64; m++) {
                float e = __expf(sc[tid][m] - mx);
                sc[tid][m] = e; sum += e;
            }
            float inv = 1.0f / sum;
#pragma unroll 8
            for (int m = 0; m < 64; m++) sc[tid][m] *= inv;
        }
        __syncthreads();

        {
            float o[8] = {0,0,0,0,0,0,0,0};
#pragma unroll 8
            for (int m = 0; m < 64; m++) {
                float p = sc[n][m];
#pragma unroll
                for (int q = 0; q < 8; q++) o[q] += p * vsm[m][d0 + q];
            }
            float* op = O + (size_t)tok[n] * C_DIM + h * 32 + d0;
#pragma unroll
            for (int q = 0; q < 8; q++) op[q] = tf32r(o[q]);
        }
        __syncthreads();
    }
}

// ---------------------------------------------------------------------------
static void run_block(const float* Xin, float* Xout,
                      const float* g1, const float* b1,
                      const float* qw, const float* qb, const float* rpb,
                      const float* pw, const float* pb,
                      const float* g2, const float* b2,
                      const float* f1w, const float* f1b,
                      const float* f2w, const float* f2b,
                      int shifted,
                      float* bufA, float* qkv, float* obuf, float* bufT)
{
    dim3 lnBlk(32, 8);
    int lnGrid = L_TOK / 8;

    ln_kernel<<<lnGrid, lnBlk>>>(Xin, g1, b1, bufA);
    gemm_tf32<false, false, false><<<dim3(QKV_DIM / GBN, L_TOK / GBM), 256>>>(
        bufA, qw, qb, nullptr, qkv, L_TOK, QKV_DIM, C_DIM);
    attn_kernel<<<NWIN, 256>>>(qkv, rpb, obuf, shifted);
    gemm_tf32<false, true, false><<<dim3(C_DIM / GBN, L_TOK / GBM), 256>>>(
        obuf, pw, pb, Xin, Xout, L_TOK, C_DIM, C_DIM);
    ln_kernel<<<lnGrid, lnBlk>>>(Xout, g2, b2, bufA);
    gemm_tf32<true, false, true><<<dim3(FF_DIM / GBN, L_TOK / GBM), 256>>>(
        bufA, f1w, f1b, nullptr, bufT, L_TOK, FF_DIM, C_DIM);
    gemm_tf32<false, true, false><<<dim3(C_DIM / GBN, L_TOK / GBM), 256>>>(
        bufT, f2w, f2b, Xout, Xout, L_TOK, C_DIM, FF_DIM);
}

extern "C" void kernel_launch(void* const* d_in, const int* in_sizes, int n_in,
                              void* d_out, int out_size)
{
    (void)in_sizes; (void)n_in; (void)out_size;
    const float* x = (const float*)d_in[0];
    float* out = (float*)d_out;

    float *bufA, *qkv, *obuf, *bufT, *wtf;
    cudaGetSymbolAddress((void**)&bufA, g_bufA);
    cudaGetSymbolAddress((void**)&qkv,  g_qkv);
    cudaGetSymbolAddress((void**)&obuf, g_obuf);
    cudaGetSymbolAddress((void**)&bufT, g_bufT);
    cudaGetSymbolAddress((void**)&wtf,  g_wtf);

    // tf32 weight copy layout per block: qw | pw | f1w | f2w
    const int SZ_QW = C_DIM * QKV_DIM;   // 110592
    const int SZ_PW = C_DIM * C_DIM;     // 36864
    const int SZ_F1 = C_DIM * FF_DIM;    // 147456
    const int SZ_F2 = FF_DIM * C_DIM;    // 147456
    const int BLK   = SZ_QW + SZ_PW + SZ_F1 + SZ_F2;  // 442368

    const int widx[2][4] = { {3, 6, 10, 12}, {16, 19, 23, 25} };
    const int wsz[4] = { SZ_QW, SZ_PW, SZ_F1, SZ_F2 };
    float* wp[2][4];
    for (int b = 0; b < 2; b++) {
        int off = b * BLK;
        for (int w = 0; w < 4; w++) {
            wp[b][w] = wtf + off;
            cvt_tf32_kernel<<<(wsz[w] + 255) / 256, 256>>>(
                (const float*)d_in[widx[b][w]], wp[b][w], wsz[w]);
            off += wsz[w];
        }
    }

    run_block(x, out,
              (const float*)d_in[1],  (const float*)d_in[2],
              wp[0][0],               (const float*)d_in[4],  (const float*)d_in[5],
              wp[0][1],               (const float*)d_in[7],
              (const float*)d_in[8],  (const float*)d_in[9],
              wp[0][2],               (const float*)d_in[11],
              wp[0][3],               (const float*)d_in[13],
              0, bufA, qkv, obuf, bufT);

    run_block(out, out,
              (const float*)d_in[14], (const float*)d_in[15],
              wp[1][0],               (const float*)d_in[17], (const float*)d_in[18],
              wp[1][1],               (const float*)d_in[20],
              (const float*)d_in[21], (const float*)d_in[22],
              wp[1][2],               (const float*)d_in[24],
              wp[1][3],               (const float*)d_in[26],
              1, bufA, qkv, obuf, bufT);
}

// round 4
// speedup vs baseline: 2.1521x; 1.1301x over previous
#include <cuda_runtime.h>
#include <math.h>

#define L_TOK 131072
#define C_DIM 192
#define QKV_DIM 576
#define FF_DIM 768
#define NWIN 2048

__device__ float g_bufA[(size_t)L_TOK * C_DIM];    // LN out (tf32-rounded)
__device__ float g_qkv [(size_t)L_TOK * QKV_DIM];  // QKV
__device__ float g_obuf[(size_t)L_TOK * C_DIM];    // attn out (tf32-rounded)
__device__ float g_bufT[(size_t)L_TOK * FF_DIM];   // MLP hidden (tf32-rounded)
__device__ float g_wtf [884736];                   // tf32 weight copies

__device__ __forceinline__ float tf32r(float x) {
    unsigned u;
    asm("cvt.rna.tf32.f32 %0, %1;" : "=r"(u) : "f"(x));
    return __uint_as_float(u);
}

__device__ __forceinline__ void cp_async16(void* smem, const void* gmem) {
    unsigned saddr = (unsigned)__cvta_generic_to_shared(smem);
    asm volatile("cp.async.cg.shared.global [%0], [%1], 16;\n" :: "r"(saddr), "l"(gmem));
}

__global__ void cvt_tf32_kernel(const float* __restrict__ in,
                                float* __restrict__ out, int n)
{
    int i = blockIdx.x * 256 + threadIdx.x;
    if (i < n) out[i] = tf32r(in[i]);
}

// ---------------------------------------------------------------------------
// LayerNorm, one row per warp; output tf32-rounded (feeds GEMM A only)
// ---------------------------------------------------------------------------
__global__ void ln_kernel(const float* __restrict__ x,
                          const float* __restrict__ g,
                          const float* __restrict__ b,
                          float* __restrict__ out)
{
    int row  = blockIdx.x * 8 + threadIdx.y;
    int lane = threadIdx.x;
    const float* xr = x + (size_t)row * C_DIM;
    float v[6];
    float s = 0.f;
#pragma unroll
    for (int i = 0; i < 6; i++) { v[i] = xr[lane + i * 32]; s += v[i]; }
#pragma unroll
    for (int o = 16; o; o >>= 1) s += __shfl_xor_sync(0xffffffffu, s, o);
    float mu = s * (1.0f / 192.0f);
    float vs = 0.f;
#pragma unroll
    for (int i = 0; i < 6; i++) { float d = v[i] - mu; vs += d * d; }
#pragma unroll
    for (int o = 16; o; o >>= 1) vs += __shfl_xor_sync(0xffffffffu, vs, o);
    float rstd = rsqrtf(vs * (1.0f / 192.0f) + 1e-5f);
    float* orow = out + (size_t)row * C_DIM;
#pragma unroll
    for (int i = 0; i < 6; i++) {
        int c = lane + i * 32;
        orow[c] = tf32r((v[i] - mu) * rstd * g[c] + b[c]);
    }
}

// ---------------------------------------------------------------------------
// TF32 GEMM: BM=128, BN=192, BK=16, 256 thr, 8 warps (4x2), warp tile 32x96.
// ---------------------------------------------------------------------------
#define GBM 128
#define GBN 192
#define GBK 16
#define ASTR 20
#define BSTR 200

template<bool DOGELU, bool RES, bool OTF>
__global__ __launch_bounds__(256, 1)
void gemm_tf32(const float* __restrict__ A, const float* __restrict__ B,
               const float* __restrict__ bias, const float* __restrict__ res,
               float* __restrict__ Cout, int M, int N, int K)
{
    __shared__ float As[2][GBM * ASTR];
    __shared__ float Bs[2][GBK * BSTR];

    int tid = threadIdx.x;
    int bm = blockIdx.y * GBM;
    int bn = blockIdx.x * GBN;
    int wid = tid >> 5, lane = tid & 31;
    int wm = (wid & 3) * 32, wn = (wid >> 2) * 96;
    int g = lane >> 2, t = lane & 3;

    float acc[2][12][4];
#pragma unroll
    for (int a = 0; a < 2; a++)
#pragma unroll
        for (int b2 = 0; b2 < 12; b2++)
#pragma unroll
            for (int c = 0; c < 4; c++) acc[a][b2][c] = 0.f;

    auto loadA = [&](int stage, int k0) {
#pragma unroll
        for (int l = 0; l < 2; l++) {
            int idx = tid + l * 256;        // 0..511 : 128 rows x 4 float4
            int m  = idx >> 2;
            int k4 = (idx & 3) * 4;
            cp_async16(&As[stage][m * ASTR + k4],
                       A + (size_t)(bm + m) * K + k0 + k4);
        }
    };
    auto loadB = [&](int stage, int k0) {
#pragma unroll
        for (int l = 0; l < 3; l++) {
            int idx = tid + l * 256;        // 0..767 : 16 rows x 48 float4
            int r  = idx / 48;
            int c4 = (idx % 48) * 4;
            cp_async16(&Bs[stage][r * BSTR + c4],
                       B + (size_t)(k0 + r) * N + bn + c4);
        }
    };

    int nk = K / GBK;
    loadA(0, 0); loadB(0, 0);
    asm volatile("cp.async.commit_group;");

    for (int kb = 0; kb < nk; kb++) {
        if (kb + 1 < nk) {
            loadA((kb + 1) & 1, (kb + 1) * GBK);
            loadB((kb + 1) & 1, (kb + 1) * GBK);
            asm volatile("cp.async.commit_group;");
            asm volatile("cp.async.wait_group 1;");
        } else {
            asm volatile("cp.async.wait_group 0;");
        }
        __syncthreads();

        const float* as = As[kb & 1];
        const float* bs = Bs[kb & 1];
#pragma unroll
        for (int ks = 0; ks < 2; ks++) {
            unsigned af[2][4], bf[12][2];
#pragma unroll
            for (int mt = 0; mt < 2; mt++) {
                int mb = wm + mt * 16;
                af[mt][0] = __float_as_uint(as[(mb + g    ) * ASTR + ks * 8 + t    ]);
                af[mt][1] = __float_as_uint(as[(mb + g + 8) * ASTR + ks * 8 + t    ]);
                af[mt][2] = __float_as_uint(as[(mb + g    ) * ASTR + ks * 8 + t + 4]);
                af[mt][3] = __float_as_uint(as[(mb + g + 8) * ASTR + ks * 8 + t + 4]);
            }
#pragma unroll
            for (int nt = 0; nt < 12; nt++) {
                int nb = wn + nt * 8 + g;
                bf[nt][0] = __float_as_uint(bs[(ks * 8 + t    ) * BSTR + nb]);
                bf[nt][1] = __float_as_uint(bs[(ks * 8 + t + 4) * BSTR + nb]);
            }
#pragma unroll
            for (int mt = 0; mt < 2; mt++)
#pragma unroll
                for (int nt = 0; nt < 12; nt++) {
                    asm volatile(
                        "mma.sync.aligned.m16n8k8.row.col.f32.tf32.tf32.f32 "
                        "{%0,%1,%2,%3},{%4,%5,%6,%7},{%8,%9},{%0,%1,%2,%3};"
                        : "+f"(acc[mt][nt][0]), "+f"(acc[mt][nt][1]),
                          "+f"(acc[mt][nt][2]), "+f"(acc[mt][nt][3])
                        : "r"(af[mt][0]), "r"(af[mt][1]),
                          "r"(af[mt][2]), "r"(af[mt][3]),
                          "r"(bf[nt][0]), "r"(bf[nt][1]));
                }
        }
        __syncthreads();
    }

#pragma unroll
    for (int mt = 0; mt < 2; mt++)
#pragma unroll
        for (int nt = 0; nt < 12; nt++) {
            int col = bn + wn + nt * 8 + 2 * t;
            float2 bv = *(const float2*)(bias + col);
#pragma unroll
            for (int hf = 0; hf < 2; hf++) {
                int row = bm + wm + mt * 16 + g + hf * 8;
                float x0 = acc[mt][nt][hf * 2 + 0] + bv.x;
                float x1 = acc[mt][nt][hf * 2 + 1] + bv.y;
                if (DOGELU) {
                    x0 = 0.5f * x0 * (1.0f + erff(x0 * 0.70710678118654752f));
                    x1 = 0.5f * x1 * (1.0f + erff(x1 * 0.70710678118654752f));
                }
                if (RES) {
                    float2 r = *(const float2*)(res + (size_t)row * N + col);
                    x0 += r.x; x1 += r.y;
                }
                if (OTF) { x0 = tf32r(x0); x1 = tf32r(x1); }
                *(float2*)(Cout + (size_t)row * N + col) = make_float2(x0, x1);
            }
        }
}

// ---------------------------------------------------------------------------
// Window attention. q row kept in registers (loaded straight from gmem),
// K/V staged in smem (stride 36 floats, float4), rpb staged in smem,
// quad-parallel softmax, 1/sum deferred to PV epilogue.
// Smem: 9216+9216+16640+8232+768 = 44072 B (< 48K).
// ---------------------------------------------------------------------------
__global__ __launch_bounds__(256)
void attn_kernel(const float* __restrict__ qkv, const float* __restrict__ rpb,
                 float* __restrict__ O, int shifted)
{
    __shared__ float ks[64 * 36];
    __shared__ float vs[64 * 36];
    __shared__ float sc[64 * 65];
    __shared__ float rpbs[2058];       // 343 x 6
    __shared__ float rinv[64];
    __shared__ int tok[64];
    __shared__ int regid[64];

    int win = blockIdx.x;
    int ws = win >> 8;
    int wh = (win >> 4) & 15;
    int ww = win & 15;
    int tid = threadIdx.x;

    if (tid < 64) {
        int i = tid >> 4, j = (tid >> 2) & 3, k = tid & 3;
        int cs = ws * 4 + i, ch = wh * 4 + j, cw = ww * 4 + k;
        int sg, hg, wg;
        if (shifted) { sg = (cs + 2) & 31; hg = (ch + 2) & 63; wg = (cw + 2) & 63; }
        else         { sg = cs;            hg = ch;            wg = cw; }
        tok[tid] = (sg * 64 + hg) * 64 + wg;
        int rs = cs < 28 ? 0 : (cs < 30 ? 1 : 2);
        int rh = ch < 60 ? 0 : (ch < 62 ? 1 : 2);
        int rw = cw < 60 ? 0 : (cw < 62 ? 1 : 2);
        regid[tid] = rs * 9 + rh * 3 + rw;
    }
    for (int i = tid; i < 2058; i += 256) rpbs[i] = rpb[i];
    __syncthreads();

    const float scale = 0.17677669529663687f;
    int n  = tid >> 2;
    int t4 = tid & 3;
    int d0 = t4 * 8;
    int myreg = regid[n];
    int in_ = n >> 4, jn = (n >> 2) & 3, kn = n & 3;
    const float* rowbase = qkv + (size_t)tok[n] * QKV_DIM;

    for (int h = 0; h < 6; h++) {
        // ---- stage k, v into smem (float4); q row straight to registers ----
        {
            const float* base = rowbase + h * 32 + d0;
            *(float4*)(&ks[n * 36 + d0])     = *(const float4*)(base + 192);
            *(float4*)(&ks[n * 36 + d0 + 4]) = *(const float4*)(base + 196);
            *(float4*)(&vs[n * 36 + d0])     = *(const float4*)(base + 384);
            *(float4*)(&vs[n * 36 + d0 + 4]) = *(const float4*)(base + 388);
        }
        float4 qr[8];
        {
            const float* qb = rowbase + h * 32;
#pragma unroll
            for (int j = 0; j < 8; j++) {
                float4 q = *(const float4*)(qb + j * 4);
                q.x *= scale; q.y *= scale; q.z *= scale; q.w *= scale;
                qr[j] = q;
            }
        }
        __syncthreads();

        // ---- scores: m = tI*4 + t4 (conflict-free LDS.128 on ks) ----
#pragma unroll 4
        for (int tI = 0; tI < 16; tI++) {
            int m = tI * 4 + t4;
            float s = 0.f;
#pragma unroll
            for (int j = 0; j < 8; j++) {
                float4 kk = *(const float4*)(&ks[m * 36 + j * 4]);
                s += qr[j].x * kk.x + qr[j].y * kk.y + qr[j].z * kk.z + qr[j].w * kk.w;
            }
            int im = m >> 4, jm = (m >> 2) & 3, km = m & 3;
            int idx = (in_ - im + 3) * 49 + (jn - jm + 3) * 7 + (kn - km + 3);
            s += rpbs[idx * 6 + h];
            if (shifted && (myreg != regid[m])) s -= 100.f;
            sc[n * 65 + m] = s;
        }
        __syncthreads();

        // ---- quad-parallel softmax (unnormalized exp; 1/sum stored) ----
        {
            float mx = -1e30f;
#pragma unroll
            for (int i = 0; i < 16; i++) mx = fmaxf(mx, sc[n * 65 + t4 * 16 + i]);
            mx = fmaxf(mx, __shfl_xor_sync(0xffffffffu, mx, 1));
            mx = fmaxf(mx, __shfl_xor_sync(0xffffffffu, mx, 2));
            float sum = 0.f;
#pragma unroll
            for (int i = 0; i < 16; i++) {
                int o = n * 65 + t4 * 16 + i;
                float e = __expf(sc[o] - mx);
                sc[o] = e; sum += e;
            }
            sum += __shfl_xor_sync(0xffffffffu, sum, 1);
            sum += __shfl_xor_sync(0xffffffffu, sum, 2);
            if (t4 == 0) rinv[n] = 1.0f / sum;
        }
        __syncthreads();

        // ---- O = P @ V (normalize at the end) ----
        {
            float4 o0 = make_float4(0, 0, 0, 0);
            float4 o1 = make_float4(0, 0, 0, 0);
#pragma unroll 8
            for (int m = 0; m < 64; m++) {
                float p = sc[n * 65 + m];
                float4 v0 = *(const float4*)(&vs[m * 36 + d0]);
                float4 v1 = *(const float4*)(&vs[m * 36 + d0 + 4]);
                o0.x += p * v0.x; o0.y += p * v0.y; o0.z += p * v0.z; o0.w += p * v0.w;
                o1.x += p * v1.x; o1.y += p * v1.y; o1.z += p * v1.z; o1.w += p * v1.w;
            }
            float inv = rinv[n];
            float* op = O + (size_t)tok[n] * C_DIM + h * 32 + d0;
            op[0] = tf32r(o0.x * inv); op[1] = tf32r(o0.y * inv);
            op[2] = tf32r(o0.z * inv); op[3] = tf32r(o0.w * inv);
            op[4] = tf32r(o1.x * inv); op[5] = tf32r(o1.y * inv);
            op[6] = tf32r(o1.z * inv); op[7] = tf32r(o1.w * inv);
        }
        __syncthreads();
    }
}

// ---------------------------------------------------------------------------
static void run_block(const float* Xin, float* Xout,
                      const float* g1, const float* b1,
                      const float* qw, const float* qb, const float* rpb,
                      const float* pw, const float* pb,
                      const float* g2, const float* b2,
                      const float* f1w, const float* f1b,
                      const float* f2w, const float* f2b,
                      int shifted,
                      float* bufA, float* qkv, float* obuf, float* bufT)
{
    dim3 lnBlk(32, 8);
    int lnGrid = L_TOK / 8;

    ln_kernel<<<lnGrid, lnBlk>>>(Xin, g1, b1, bufA);
    gemm_tf32<false, false, false><<<dim3(QKV_DIM / GBN, L_TOK / GBM), 256>>>(
        bufA, qw, qb, nullptr, qkv, L_TOK, QKV_DIM, C_DIM);
    attn_kernel<<<NWIN, 256>>>(qkv, rpb, obuf, shifted);
    gemm_tf32<false, true, false><<<dim3(C_DIM / GBN, L_TOK / GBM), 256>>>(
        obuf, pw, pb, Xin, Xout, L_TOK, C_DIM, C_DIM);
    ln_kernel<<<lnGrid, lnBlk>>>(Xout, g2, b2, bufA);
    gemm_tf32<true, false, true><<<dim3(FF_DIM / GBN, L_TOK / GBM), 256>>>(
        bufA, f1w, f1b, nullptr, bufT, L_TOK, FF_DIM, C_DIM);
    gemm_tf32<false, true, false><<<dim3(C_DIM / GBN, L_TOK / GBM), 256>>>(
        bufT, f2w, f2b, Xout, Xout, L_TOK, C_DIM, FF_DIM);
}

extern "C" void kernel_launch(void* const* d_in, const int* in_sizes, int n_in,
                              void* d_out, int out_size)
{
    (void)in_sizes; (void)n_in; (void)out_size;
    const float* x = (const float*)d_in[0];
    float* out = (float*)d_out;

    float *bufA, *qkv, *obuf, *bufT, *wtf;
    cudaGetSymbolAddress((void**)&bufA, g_bufA);
    cudaGetSymbolAddress((void**)&qkv,  g_qkv);
    cudaGetSymbolAddress((void**)&obuf, g_obuf);
    cudaGetSymbolAddress((void**)&bufT, g_bufT);
    cudaGetSymbolAddress((void**)&wtf,  g_wtf);

    const int SZ_QW = C_DIM * QKV_DIM;
    const int SZ_PW = C_DIM * C_DIM;
    const int SZ_F1 = C_DIM * FF_DIM;
    const int SZ_F2 = FF_DIM * C_DIM;
    const int BLK   = SZ_QW + SZ_PW + SZ_F1 + SZ_F2;

    const int widx[2][4] = { {3, 6, 10, 12}, {16, 19, 23, 25} };
    const int wsz[4] = { SZ_QW, SZ_PW, SZ_F1, SZ_F2 };
    float* wp[2][4];
    for (int b = 0; b < 2; b++) {
        int off = b * BLK;
        for (int w = 0; w < 4; w++) {
            wp[b][w] = wtf + off;
            cvt_tf32_kernel<<<(wsz[w] + 255) / 256, 256>>>(
                (const float*)d_in[widx[b][w]], wp[b][w], wsz[w]);
            off += wsz[w];
        }
    }

    run_block(x, out,
              (const float*)d_in[1],  (const float*)d_in[2],
              wp[0][0],               (const float*)d_in[4],  (const float*)d_in[5],
              wp[0][1],               (const float*)d_in[7],
              (const float*)d_in[8],  (const float*)d_in[9],
              wp[0][2],               (const float*)d_in[11],
              wp[0][3],               (const float*)d_in[13],
              0, bufA, qkv, obuf, bufT);

    run_block(out, out,
              (const float*)d_in[14], (const float*)d_in[15],
              wp[1][0],               (const float*)d_in[17], (const float*)d_in[18],
              wp[1][1],               (const float*)d_in[20],
              (const float*)d_in[21], (const float*)d_in[22],
              wp[1][2],               (const float*)d_in[24],
              wp[1][3],               (const float*)d_in[26],
              1, bufA, qkv, obuf, bufT);
}

// round 5
// speedup vs baseline: 2.8834x; 1.3398x over previous
#include <cuda_runtime.h>
#include <cuda_bf16.h>
#include <math.h>

#define L_TOK 131072
#define C_DIM 192
#define QKV_DIM 576
#define FF_DIM 768
#define NWIN 2048

// scratch (device globals)
__device__ __nv_bfloat16 g_bufA[(size_t)L_TOK * C_DIM];   // LN out
__device__ float         g_qkv [(size_t)L_TOK * QKV_DIM]; // QKV (fp32)
__device__ __nv_bfloat16 g_obuf[(size_t)L_TOK * C_DIM];   // attn out
__device__ __nv_bfloat16 g_bufT[(size_t)L_TOK * FF_DIM];  // MLP hidden
__device__ __nv_bfloat16 g_wbf [884736];                  // bf16 weights

__device__ __forceinline__ void cp_async16(void* smem, const void* gmem) {
    unsigned saddr = (unsigned)__cvta_generic_to_shared(smem);
    asm volatile("cp.async.cg.shared.global [%0], [%1], 16;\n" :: "r"(saddr), "l"(gmem));
}

__device__ __forceinline__ void ldsm_x4(unsigned& r0, unsigned& r1,
                                        unsigned& r2, unsigned& r3, unsigned addr) {
    asm volatile("ldmatrix.sync.aligned.m8n8.x4.shared.b16 {%0,%1,%2,%3}, [%4];"
                 : "=r"(r0), "=r"(r1), "=r"(r2), "=r"(r3) : "r"(addr));
}
__device__ __forceinline__ void ldsm_x4_t(unsigned& r0, unsigned& r1,
                                          unsigned& r2, unsigned& r3, unsigned addr) {
    asm volatile("ldmatrix.sync.aligned.m8n8.x4.trans.shared.b16 {%0,%1,%2,%3}, [%4];"
                 : "=r"(r0), "=r"(r1), "=r"(r2), "=r"(r3) : "r"(addr));
}

__global__ void cvt_bf16_kernel(const float* __restrict__ in,
                                __nv_bfloat16* __restrict__ out, int n)
{
    int i = blockIdx.x * 256 + threadIdx.x;
    if (i < n) out[i] = __float2bfloat16(in[i]);
}

// ---------------------------------------------------------------------------
// LayerNorm, one row per warp; bf16 output (feeds GEMM A)
// ---------------------------------------------------------------------------
__global__ void ln_kernel(const float* __restrict__ x,
                          const float* __restrict__ g,
                          const float* __restrict__ b,
                          __nv_bfloat16* __restrict__ out)
{
    int row  = blockIdx.x * 8 + threadIdx.y;
    int lane = threadIdx.x;
    const float* xr = x + (size_t)row * C_DIM;
    float v[6];
    float s = 0.f;
#pragma unroll
    for (int i = 0; i < 6; i++) { v[i] = xr[lane + i * 32]; s += v[i]; }
#pragma unroll
    for (int o = 16; o; o >>= 1) s += __shfl_xor_sync(0xffffffffu, s, o);
    float mu = s * (1.0f / 192.0f);
    float vs = 0.f;
#pragma unroll
    for (int i = 0; i < 6; i++) { float d = v[i] - mu; vs += d * d; }
#pragma unroll
    for (int o = 16; o; o >>= 1) vs += __shfl_xor_sync(0xffffffffu, vs, o);
    float rstd = rsqrtf(vs * (1.0f / 192.0f) + 1e-5f);
    __nv_bfloat16* orow = out + (size_t)row * C_DIM;
#pragma unroll
    for (int i = 0; i < 6; i++) {
        int c = lane + i * 32;
        orow[c] = __float2bfloat16((v[i] - mu) * rstd * g[c] + b[c]);
    }
}

// ---------------------------------------------------------------------------
// bf16 GEMM: BM=128, BN=192, BK=32. 256 thr, 8 warps (4x2), warp tile 32x96.
// mma.sync.m16n8k16 + ldmatrix. fp32 accumulate. Smem 46080 B.
// ---------------------------------------------------------------------------
#define GBM 128
#define GBN 192
#define GBK 32
#define ASTRH 40    // bf16 elems per A smem row (32+8)
#define BSTRH 200   // bf16 elems per B smem row (192+8)
#define ASTAGE (GBM * ASTRH * 2)   // 10240 B
#define BSTAGE (GBK * BSTRH * 2)   // 12800 B

template<bool DOGELU, bool RES, bool OUTBF>
__global__ __launch_bounds__(256, 1)
void gemm_bf16(const __nv_bfloat16* __restrict__ A,
               const __nv_bfloat16* __restrict__ B,
               const float* __restrict__ bias, const float* __restrict__ res,
               void* __restrict__ Cout, int M, int N, int K)
{
    __shared__ __nv_bfloat16 As[2][GBM * ASTRH];
    __shared__ __nv_bfloat16 Bs[2][GBK * BSTRH];

    int tid = threadIdx.x;
    int bm = blockIdx.y * GBM;
    int bn = blockIdx.x * GBN;
    int wid = tid >> 5, lane = tid & 31;
    int wm = (wid & 3) * 32, wn = (wid >> 2) * 96;
    int g = lane >> 2, t = lane & 3;

    // ldmatrix lane address components (same formula for A and B-trans)
    int ldrow = (lane & 7) + ((lane >> 3) & 1) * 8;   // row-in-tilepair
    int ldcol = (lane >> 4) * 8;                       // col offset (8 or 0)

    unsigned sA0 = (unsigned)__cvta_generic_to_shared(&As[0][0]);
    unsigned sB0 = (unsigned)__cvta_generic_to_shared(&Bs[0][0]);
    unsigned aBase = sA0 + (unsigned)(((wm + ldrow) * ASTRH + ldcol) * 2);
    unsigned bBase = sB0 + (unsigned)((ldrow * BSTRH + wn + ldcol) * 2);

    float acc[2][12][4];
#pragma unroll
    for (int a = 0; a < 2; a++)
#pragma unroll
        for (int j = 0; j < 12; j++)
#pragma unroll
            for (int c = 0; c < 4; c++) acc[a][j][c] = 0.f;

    auto loadA = [&](int stage, int k0) {
#pragma unroll
        for (int l = 0; l < 2; l++) {
            int idx = tid + l * 256;        // 0..511 : 128 rows x 4 chunks(8 bf16)
            int m = idx >> 2;
            int c = (idx & 3) * 8;
            cp_async16(&As[stage][m * ASTRH + c],
                       A + (size_t)(bm + m) * K + k0 + c);
        }
    };
    auto loadB = [&](int stage, int k0) {
#pragma unroll
        for (int l = 0; l < 3; l++) {
            int idx = tid + l * 256;        // 0..767 : 32 rows x 24 chunks
            int r = idx / 24;
            int c = (idx % 24) * 8;
            cp_async16(&Bs[stage][r * BSTRH + c],
                       B + (size_t)(k0 + r) * N + bn + c);
        }
    };

    int nk = K / GBK;
    loadA(0, 0); loadB(0, 0);
    asm volatile("cp.async.commit_group;");

    for (int kb = 0; kb < nk; kb++) {
        if (kb + 1 < nk) {
            loadA((kb + 1) & 1, (kb + 1) * GBK);
            loadB((kb + 1) & 1, (kb + 1) * GBK);
            asm volatile("cp.async.commit_group;");
            asm volatile("cp.async.wait_group 1;");
        } else {
            asm volatile("cp.async.wait_group 0;");
        }
        __syncthreads();

        unsigned aS = aBase + (kb & 1) * ASTAGE;
        unsigned bS = bBase + (kb & 1) * BSTAGE;
#pragma unroll
        for (int ks = 0; ks < 2; ks++) {
            unsigned af[2][4], bfr[6][4];
#pragma unroll
            for (int mt = 0; mt < 2; mt++)
                ldsm_x4(af[mt][0], af[mt][1], af[mt][2], af[mt][3],
                        aS + mt * (16 * ASTRH * 2) + ks * 32);
#pragma unroll
            for (int nt = 0; nt < 6; nt++)
                ldsm_x4_t(bfr[nt][0], bfr[nt][1], bfr[nt][2], bfr[nt][3],
                          bS + ks * (16 * BSTRH * 2) + nt * 32);
#pragma unroll
            for (int mt = 0; mt < 2; mt++)
#pragma unroll
                for (int nt = 0; nt < 6; nt++) {
                    asm volatile(
                        "mma.sync.aligned.m16n8k16.row.col.f32.bf16.bf16.f32 "
                        "{%0,%1,%2,%3},{%4,%5,%6,%7},{%8,%9},{%0,%1,%2,%3};"
                        : "+f"(acc[mt][nt * 2][0]), "+f"(acc[mt][nt * 2][1]),
                          "+f"(acc[mt][nt * 2][2]), "+f"(acc[mt][nt * 2][3])
                        : "r"(af[mt][0]), "r"(af[mt][1]),
                          "r"(af[mt][2]), "r"(af[mt][3]),
                          "r"(bfr[nt][0]), "r"(bfr[nt][1]));
                    asm volatile(
                        "mma.sync.aligned.m16n8k16.row.col.f32.bf16.bf16.f32 "
                        "{%0,%1,%2,%3},{%4,%5,%6,%7},{%8,%9},{%0,%1,%2,%3};"
                        : "+f"(acc[mt][nt * 2 + 1][0]), "+f"(acc[mt][nt * 2 + 1][1]),
                          "+f"(acc[mt][nt * 2 + 1][2]), "+f"(acc[mt][nt * 2 + 1][3])
                        : "r"(af[mt][0]), "r"(af[mt][1]),
                          "r"(af[mt][2]), "r"(af[mt][3]),
                          "r"(bfr[nt][2]), "r"(bfr[nt][3]));
                }
        }
        __syncthreads();
    }

    // epilogue: j-th n8 tile; c0,c1 -> (row g, cols 2t,2t+1); c2,c3 -> row g+8
#pragma unroll
    for (int mt = 0; mt < 2; mt++)
#pragma unroll
        for (int j = 0; j < 12; j++) {
            int col = bn + wn + j * 8 + 2 * t;
            float2 bv = *(const float2*)(bias + col);
#pragma unroll
            for (int hf = 0; hf < 2; hf++) {
                int row = bm + wm + mt * 16 + g + hf * 8;
                float x0 = acc[mt][j][hf * 2 + 0] + bv.x;
                float x1 = acc[mt][j][hf * 2 + 1] + bv.y;
                if (DOGELU) {
                    x0 = 0.5f * x0 * (1.0f + erff(x0 * 0.70710678118654752f));
                    x1 = 0.5f * x1 * (1.0f + erff(x1 * 0.70710678118654752f));
                }
                if (RES) {
                    float2 r = *(const float2*)(res + (size_t)row * N + col);
                    x0 += r.x; x1 += r.y;
                }
                if (OUTBF) {
                    __nv_bfloat162* p = (__nv_bfloat162*)
                        ((__nv_bfloat16*)Cout + (size_t)row * N + col);
                    *p = __floats2bfloat162_rn(x0, x1);
                } else {
                    *(float2*)((float*)Cout + (size_t)row * N + col)
                        = make_float2(x0, x1);
                }
            }
        }
}

// ---------------------------------------------------------------------------
// Window attention (fp32 math), bf16 output. q in regs, K/V smem, rpb smem.
// ---------------------------------------------------------------------------
__global__ __launch_bounds__(256)
void attn_kernel(const float* __restrict__ qkv, const float* __restrict__ rpb,
                 __nv_bfloat16* __restrict__ O, int shifted)
{
    __shared__ float ks[64 * 36];
    __shared__ float vs[64 * 36];
    __shared__ float sc[64 * 65];
    __shared__ float rpbs[2058];       // 343 x 6
    __shared__ float rinv[64];
    __shared__ int tok[64];
    __shared__ int regid[64];

    int win = blockIdx.x;
    int ws = win >> 8;
    int wh = (win >> 4) & 15;
    int ww = win & 15;
    int tid = threadIdx.x;

    if (tid < 64) {
        int i = tid >> 4, j = (tid >> 2) & 3, k = tid & 3;
        int cs = ws * 4 + i, ch = wh * 4 + j, cw = ww * 4 + k;
        int sg, hg, wg;
        if (shifted) { sg = (cs + 2) & 31; hg = (ch + 2) & 63; wg = (cw + 2) & 63; }
        else         { sg = cs;            hg = ch;            wg = cw; }
        tok[tid] = (sg * 64 + hg) * 64 + wg;
        int rs = cs < 28 ? 0 : (cs < 30 ? 1 : 2);
        int rh = ch < 60 ? 0 : (ch < 62 ? 1 : 2);
        int rw = cw < 60 ? 0 : (cw < 62 ? 1 : 2);
        regid[tid] = rs * 9 + rh * 3 + rw;
    }
    for (int i = tid; i < 2058; i += 256) rpbs[i] = rpb[i];
    __syncthreads();

    const float scale = 0.17677669529663687f;
    int n  = tid >> 2;
    int t4 = tid & 3;
    int d0 = t4 * 8;
    int myreg = regid[n];
    int in_ = n >> 4, jn = (n >> 2) & 3, kn = n & 3;
    const float* rowbase = qkv + (size_t)tok[n] * QKV_DIM;

    for (int h = 0; h < 6; h++) {
        {
            const float* base = rowbase + h * 32 + d0;
            *(float4*)(&ks[n * 36 + d0])     = *(const float4*)(base + 192);
            *(float4*)(&ks[n * 36 + d0 + 4]) = *(const float4*)(base + 196);
            *(float4*)(&vs[n * 36 + d0])     = *(const float4*)(base + 384);
            *(float4*)(&vs[n * 36 + d0 + 4]) = *(const float4*)(base + 388);
        }
        float4 qr[8];
        {
            const float* qb = rowbase + h * 32;
#pragma unroll
            for (int j = 0; j < 8; j++) {
                float4 q = *(const float4*)(qb + j * 4);
                q.x *= scale; q.y *= scale; q.z *= scale; q.w *= scale;
                qr[j] = q;
            }
        }
        __syncthreads();

#pragma unroll 4
        for (int tI = 0; tI < 16; tI++) {
            int m = tI * 4 + t4;
            float s = 0.f;
#pragma unroll
            for (int j = 0; j < 8; j++) {
                float4 kk = *(const float4*)(&ks[m * 36 + j * 4]);
                s += qr[j].x * kk.x + qr[j].y * kk.y + qr[j].z * kk.z + qr[j].w * kk.w;
            }
            int im = m >> 4, jm = (m >> 2) & 3, km = m & 3;
            int idx = (in_ - im + 3) * 49 + (jn - jm + 3) * 7 + (kn - km + 3);
            s += rpbs[idx * 6 + h];
            if (shifted && (myreg != regid[m])) s -= 100.f;
            sc[n * 65 + m] = s;
        }
        __syncthreads();

        {
            float mx = -1e30f;
#pragma unroll
            for (int i = 0; i < 16; i++) mx = fmaxf(mx, sc[n * 65 + t4 * 16 + i]);
            mx = fmaxf(mx, __shfl_xor_sync(0xffffffffu, mx, 1));
            mx = fmaxf(mx, __shfl_xor_sync(0xffffffffu, mx, 2));
            float sum = 0.f;
#pragma unroll
            for (int i = 0; i < 16; i++) {
                int o = n * 65 + t4 * 16 + i;
                float e = __expf(sc[o] - mx);
                sc[o] = e; sum += e;
            }
            sum += __shfl_xor_sync(0xffffffffu, sum, 1);
            sum += __shfl_xor_sync(0xffffffffu, sum, 2);
            if (t4 == 0) rinv[n] = 1.0f / sum;
        }
        __syncthreads();

        {
            float4 o0 = make_float4(0, 0, 0, 0);
            float4 o1 = make_float4(0, 0, 0, 0);
#pragma unroll 8
            for (int m = 0; m < 64; m++) {
                float p = sc[n * 65 + m];
                float4 v0 = *(const float4*)(&vs[m * 36 + d0]);
                float4 v1 = *(const float4*)(&vs[m * 36 + d0 + 4]);
                o0.x += p * v0.x; o0.y += p * v0.y; o0.z += p * v0.z; o0.w += p * v0.w;
                o1.x += p * v1.x; o1.y += p * v1.y; o1.z += p * v1.z; o1.w += p * v1.w;
            }
            float inv = rinv[n];
            __nv_bfloat162* op = (__nv_bfloat162*)
                (O + (size_t)tok[n] * C_DIM + h * 32 + d0);
            op[0] = __floats2bfloat162_rn(o0.x * inv, o0.y * inv);
            op[1] = __floats2bfloat162_rn(o0.z * inv, o0.w * inv);
            op[2] = __floats2bfloat162_rn(o1.x * inv, o1.y * inv);
            op[3] = __floats2bfloat162_rn(o1.z * inv, o1.w * inv);
        }
        __syncthreads();
    }
}

// ---------------------------------------------------------------------------
static void run_block(const float* Xin, float* Xout,
                      const float* g1, const float* b1,
                      const __nv_bfloat16* qw, const float* qb, const float* rpb,
                      const __nv_bfloat16* pw, const float* pb,
                      const float* g2, const float* b2,
                      const __nv_bfloat16* f1w, const float* f1b,
                      const __nv_bfloat16* f2w, const float* f2b,
                      int shifted,
                      __nv_bfloat16* bufA, float* qkv,
                      __nv_bfloat16* obuf, __nv_bfloat16* bufT)
{
    dim3 lnBlk(32, 8);
    int lnGrid = L_TOK / 8;

    ln_kernel<<<lnGrid, lnBlk>>>(Xin, g1, b1, bufA);
    gemm_bf16<false, false, false><<<dim3(QKV_DIM / GBN, L_TOK / GBM), 256>>>(
        bufA, qw, qb, nullptr, qkv, L_TOK, QKV_DIM, C_DIM);
    attn_kernel<<<NWIN, 256>>>(qkv, rpb, obuf, shifted);
    gemm_bf16<false, true, false><<<dim3(C_DIM / GBN, L_TOK / GBM), 256>>>(
        obuf, pw, pb, Xin, Xout, L_TOK, C_DIM, C_DIM);
    ln_kernel<<<lnGrid, lnBlk>>>(Xout, g2, b2, bufA);
    gemm_bf16<true, false, true><<<dim3(FF_DIM / GBN, L_TOK / GBM), 256>>>(
        bufA, f1w, f1b, nullptr, bufT, L_TOK, FF_DIM, C_DIM);
    gemm_bf16<false, true, false><<<dim3(C_DIM / GBN, L_TOK / GBM), 256>>>(
        bufT, f2w, f2b, Xout, Xout, L_TOK, C_DIM, FF_DIM);
}

extern "C" void kernel_launch(void* const* d_in, const int* in_sizes, int n_in,
                              void* d_out, int out_size)
{
    (void)in_sizes; (void)n_in; (void)out_size;
    const float* x = (const float*)d_in[0];
    float* out = (float*)d_out;

    __nv_bfloat16 *bufA, *obuf, *bufT, *wbf;
    float *qkv;
    cudaGetSymbolAddress((void**)&bufA, g_bufA);
    cudaGetSymbolAddress((void**)&qkv,  g_qkv);
    cudaGetSymbolAddress((void**)&obuf, g_obuf);
    cudaGetSymbolAddress((void**)&bufT, g_bufT);
    cudaGetSymbolAddress((void**)&wbf,  g_wbf);

    const int SZ_QW = C_DIM * QKV_DIM;
    const int SZ_PW = C_DIM * C_DIM;
    const int SZ_F1 = C_DIM * FF_DIM;
    const int SZ_F2 = FF_DIM * C_DIM;
    const int BLK   = SZ_QW + SZ_PW + SZ_F1 + SZ_F2;

    const int widx[2][4] = { {3, 6, 10, 12}, {16, 19, 23, 25} };
    const int wsz[4] = { SZ_QW, SZ_PW, SZ_F1, SZ_F2 };
    __nv_bfloat16* wp[2][4];
    for (int b = 0; b < 2; b++) {
        int off = b * BLK;
        for (int w = 0; w < 4; w++) {
            wp[b][w] = wbf + off;
            cvt_bf16_kernel<<<(wsz[w] + 255) / 256, 256>>>(
                (const float*)d_in[widx[b][w]], wp[b][w], wsz[w]);
            off += wsz[w];
        }
    }

    run_block(x, out,
              (const float*)d_in[1],  (const float*)d_in[2],
              wp[0][0],               (const float*)d_in[4],  (const float*)d_in[5],
              wp[0][1],               (const float*)d_in[7],
              (const float*)d_in[8],  (const float*)d_in[9],
              wp[0][2],               (const float*)d_in[11],
              wp[0][3],               (const float*)d_in[13],
              0, bufA, qkv, obuf, bufT);

    run_block(out, out,
              (const float*)d_in[14], (const float*)d_in[15],
              wp[1][0],               (const float*)d_in[17], (const float*)d_in[18],
              wp[1][1],               (const float*)d_in[20],
              (const float*)d_in[21], (const float*)d_in[22],
              wp[1][2],               (const float*)d_in[24],
              wp[1][3],               (const float*)d_in[26],
              1, bufA, qkv, obuf, bufT);
}